// round 9
// baseline (speedup 1.0000x reference)
#include <cuda_runtime.h>
#include <math.h>

#define NN 50000
#define EE 500000

// node-space tables
__device__ __align__(16) float4 g_q[NN * 32];
__device__ __align__(16) float4 g_k[NN * 32];
__device__ __align__(16) float4 g_v[NN * 32];
__device__ __align__(16) float4 g_z[NN * 96];      // [n][2][192] flat [n][384]
// per-dst aggregates (written once by k_edge2)
__device__ __align__(16) float4 g_aggT[NN * 32];   // [n][2][64]   sum w*enc
__device__ __align__(16) float4 g_aggM[NN * 64];   // [n][2][128]  sum w*msg
__device__ __align__(16) float4 g_aggV[NN * 32];   // [n][2][64]   sum w*v[src]
__device__ __align__(8)  float2 g_asum[NN];        // [n][2]       sum w
__device__ int g_is64;
// combined weights: cols [q(0) k(128) v(256) skip(384) z(512..895)]
__device__ __align__(16) float g_Wall[128 * 896];
__device__ __align__(16) float g_ball[896];
// counting-sort scratch
__device__ int g_cnt[NN];
__device__ int g_offA[NN];
__device__ int g_bsum[128];
__device__ int g_bpre[128];
__device__ int g_off[NN + 1];
__device__ int g_pos[NN];
__device__ int g_eid[EE];

static __device__ __forceinline__ float dot4(float4 a, float4 b) {
    return a.x * b.x + a.y * b.y + a.z * b.z + a.w * b.w;
}

// ---------------------------------------------------------------------------
__global__ void k_detect(const int* __restrict__ ei32) {
    int odd_or = 0;
    #pragma unroll
    for (int i = 1; i < 64; i += 2) odd_or |= ei32[i];
    g_is64 = (odd_or == 0) ? 1 : 0;
}

// ---------------------------------------------------------------------------
// Kp: build combined weight matrix [128][896] + bias [896].
// ---------------------------------------------------------------------------
__global__ void k_prep(const float* __restrict__ Wq, const float* __restrict__ bq,
                       const float* __restrict__ Wk, const float* __restrict__ bk,
                       const float* __restrict__ Wv, const float* __restrict__ bv,
                       const float* __restrict__ Ws, const float* __restrict__ bs,
                       const float* __restrict__ We)
{
    int u = blockIdx.x * 256 + threadIdx.x;
    if (u < 128 * 512) {
        int j = u >> 9, c = u & 511;
        const float* src = (c < 128) ? Wq : (c < 256) ? Wk : (c < 384) ? Wv : Ws;
        g_Wall[j * 896 + c] = src[j * 128 + (c & 127)];
    } else if (u < 128 * 896) {
        int v = u - 128 * 512;
        int j = v / 384, col = v % 384;
        int h = col / 192, d = col % 192;
        const float4* a = (const float4*)(Wq + j * 128 + h * 64);
        const float4* b = (const float4*)(We + d * 128 + h * 64);
        float acc = 0.f;
        #pragma unroll
        for (int c = 0; c < 16; c++) acc += dot4(a[c], b[c]);
        g_Wall[j * 896 + 512 + col] = acc;
    } else if (u < 128 * 896 + 896) {
        int c = u - 128 * 896;
        if (c < 512) {
            const float* src = (c < 128) ? bq : (c < 256) ? bk : (c < 384) ? bv : bs;
            g_ball[c] = src[c & 127];
        } else {
            int col = c - 512;
            int h = col / 192, d = col % 192;
            const float4* a = (const float4*)(bq + h * 64);
            const float4* b = (const float4*)(We + d * 128 + h * 64);
            float acc = 0.f;
            #pragma unroll
            for (int cc = 0; cc < 16; cc++) acc += dot4(a[cc], b[cc]);
            g_ball[c] = acc;
        }
    }
}

// ---------------------------------------------------------------------------
// K1: node GEMM [50000,128] @ [128,896]. Tile 128x128, 8x8 per thread.
// ---------------------------------------------------------------------------
__global__ void __launch_bounds__(256, 2)
k_gemm(const float* __restrict__ x, float* __restrict__ out)
{
    __shared__ float xs[32][132];   // [k][m] transposed x panel
    __shared__ float ws[32][128];   // [k][n]
    const int t = threadIdx.x;
    const int y = blockIdx.y;
    const int col0 = y * 128;

    float* dptr; int ds; int dcol0 = 0;
    if      (y == 0) { dptr = (float*)g_q; ds = 128; }
    else if (y == 1) { dptr = (float*)g_k; ds = 128; }
    else if (y == 2) { dptr = (float*)g_v; ds = 128; }
    else if (y == 3) { dptr = out;         ds = 128; }
    else { dptr = (float*)g_z; ds = 384; dcol0 = (y - 4) * 128; }

    const int m0 = blockIdx.x * 128;
    const float4* x4 = (const float4*)x;
    const int tn = t & 15, tm = t >> 4;

    float4 acc[8][2];
    #pragma unroll
    for (int r = 0; r < 8; r++) { acc[r][0] = make_float4(0.f,0.f,0.f,0.f); acc[r][1] = acc[r][0]; }

#define FMA4(A, S, Bv) { A.x += (S)*(Bv).x; A.y += (S)*(Bv).y; A.z += (S)*(Bv).z; A.w += (S)*(Bv).w; }
    for (int k0 = 0; k0 < 128; k0 += 32) {
        #pragma unroll
        for (int i = t; i < 1024; i += 256) {
            int m = i >> 3, c4 = i & 7;
            int node = m0 + m;
            float4 v = (node < NN) ? x4[(size_t)node * 32 + (k0 >> 2) + c4]
                                   : make_float4(0.f, 0.f, 0.f, 0.f);
            int kk = c4 * 4;
            xs[kk + 0][m] = v.x; xs[kk + 1][m] = v.y;
            xs[kk + 2][m] = v.z; xs[kk + 3][m] = v.w;
        }
        #pragma unroll
        for (int i = t; i < 1024; i += 256) {
            int kk = i >> 5, c4 = i & 31;
            *(float4*)&ws[kk][c4 * 4] = *(const float4*)&g_Wall[(size_t)(k0 + kk) * 896 + col0 + c4 * 4];
        }
        __syncthreads();

        #pragma unroll
        for (int kk = 0; kk < 32; kk++) {
            float4 a0 = *(const float4*)&xs[kk][tm * 8];
            float4 a1 = *(const float4*)&xs[kk][tm * 8 + 4];
            float4 b0 = *(const float4*)&ws[kk][tn * 8];
            float4 b1 = *(const float4*)&ws[kk][tn * 8 + 4];
            FMA4(acc[0][0], a0.x, b0); FMA4(acc[0][1], a0.x, b1);
            FMA4(acc[1][0], a0.y, b0); FMA4(acc[1][1], a0.y, b1);
            FMA4(acc[2][0], a0.z, b0); FMA4(acc[2][1], a0.z, b1);
            FMA4(acc[3][0], a0.w, b0); FMA4(acc[3][1], a0.w, b1);
            FMA4(acc[4][0], a1.x, b0); FMA4(acc[4][1], a1.x, b1);
            FMA4(acc[5][0], a1.y, b0); FMA4(acc[5][1], a1.y, b1);
            FMA4(acc[6][0], a1.z, b0); FMA4(acc[6][1], a1.z, b1);
            FMA4(acc[7][0], a1.w, b0); FMA4(acc[7][1], a1.w, b1);
        }
        __syncthreads();
    }
#undef FMA4

    float4 bb0 = *(const float4*)&g_ball[col0 + tn * 8];
    float4 bb1 = *(const float4*)&g_ball[col0 + tn * 8 + 4];
    #pragma unroll
    for (int r = 0; r < 8; r++) {
        int node = m0 + tm * 8 + r;
        if (node >= NN) break;
        float4 o0 = acc[r][0]; o0.x += bb0.x; o0.y += bb0.y; o0.z += bb0.z; o0.w += bb0.w;
        float4 o1 = acc[r][1]; o1.x += bb1.x; o1.y += bb1.y; o1.z += bb1.z; o1.w += bb1.w;
        float* p = dptr + (size_t)node * ds + dcol0 + tn * 8;
        *(float4*)p = o0;
        *(float4*)(p + 4) = o1;
    }
}

// ---------------------------------------------------------------------------
// Counting sort by dst
// ---------------------------------------------------------------------------
__global__ void k_hist(const void* __restrict__ ei) {
    const int e = blockIdx.x * 256 + threadIdx.x;
    if (e >= EE) return;
    int dst = g_is64 ? (int)((const long long*)ei)[EE + e] : ((const int*)ei)[EE + e];
    atomicAdd(&g_cnt[dst], 1);
}

__global__ void k_scanA() {
    __shared__ int s[512];
    const int tid = threadIdx.x;
    const int i = blockIdx.x * 512 + tid;
    int c = (i < NN) ? g_cnt[i] : 0;
    s[tid] = c;
    __syncthreads();
    #pragma unroll
    for (int o = 1; o < 512; o <<= 1) {
        int v = (tid >= o) ? s[tid - o] : 0;
        __syncthreads();
        if (tid >= o) s[tid] += v;
        __syncthreads();
    }
    if (i < NN) g_offA[i] = s[tid] - c;
    if (tid == 511) g_bsum[blockIdx.x] = s[511];
}

__global__ void k_scanB(int nchunks) {
    if (threadIdx.x == 0) {
        int run = 0;
        for (int b = 0; b < nchunks; b++) { g_bpre[b] = run; run += g_bsum[b]; }
        g_off[NN] = EE;
    }
}

__global__ void k_scanC() {
    const int i = blockIdx.x * 512 + threadIdx.x;
    if (i < NN) {
        int v = g_offA[i] + g_bpre[blockIdx.x];
        g_off[i] = v;
        g_pos[i] = v;
    }
}

__global__ void k_scatter(const void* __restrict__ ei) {
    const int e = blockIdx.x * 256 + threadIdx.x;
    if (e >= EE) return;
    int dst = g_is64 ? (int)((const long long*)ei)[EE + e] : ((const int*)ei)[EE + e];
    int p = atomicAdd(&g_pos[dst], 1);
    g_eid[p] = e;
}

// ---------------------------------------------------------------------------
// K2: warp per dst segment, lane-batched prefetch, single-edge compute with
// a 1-deep gather pipeline (next edge's loads issued before current compute).
// ---------------------------------------------------------------------------
__global__ void __launch_bounds__(256)
k_edge2(const void* __restrict__ ei,
        const float* __restrict__ tt,
        const float* __restrict__ lu,
        const float4* __restrict__ msg4,
        const float* __restrict__ tw,
        const float* __restrict__ tb)
{
    const int w = threadIdx.x >> 5, lane = threadIdx.x & 31;
    const int dst = blockIdx.x * 8 + w;
    if (dst >= NN) return;
    const int is64 = g_is64;
    const int beg = g_off[dst], end = g_off[dst + 1];

    const int lq = lane & 15;
    const float4 tw4 = ((const float4*)tw)[lq];
    const float4 tb4 = ((const float4*)tb)[lq];
    const float4 q4 = g_q[(size_t)dst * 32 + lane];
    const size_t zb0 = (size_t)dst * 96;
    const float4 za = g_z[zb0 + lane];
    const float4 zb = g_z[zb0 + 32 + lane];
    const float4 zc = g_z[zb0 + 64 + lane];

    float4 aT = make_float4(0.f, 0.f, 0.f, 0.f), aV = aT, aM0 = aT, aM1 = aT;
    float s0 = 0.f, s1 = 0.f;

    for (int base = beg; base < end; base += 32) {
        const int cnt = min(32, end - base);
        int eidl = 0, srcl = 0; float rell = 0.f;
        if (lane < cnt) {
            eidl = g_eid[base + lane];
            long long s = is64 ? ((const long long*)ei)[eidl]
                               : (long long)((const int*)ei)[eidl];
            srcl = (int)s;
            rell = tt[eidl] - lu[s];
        }

        // prime the gather pipeline with edge 0
        int eC = __shfl_sync(0xffffffffu, eidl, 0);
        int sC = __shfl_sync(0xffffffffu, srcl, 0);
        float rC = __shfl_sync(0xffffffffu, rell, 0);
        float4 k4n = g_k[(size_t)sC * 32 + lane];
        float4 v4n = g_v[(size_t)sC * 32 + lane];
        float4 m4n = msg4[(size_t)eC * 32 + lane];
        float4 xmn = msg4[(size_t)eC * 32 + (lane ^ 16)];

        for (int j = 0; j < cnt; j++) {
            const float rel = rC;
            const float4 k4 = k4n, v4 = v4n, m4 = m4n, xm = xmn;
            if (j + 1 < cnt) {
                eC = __shfl_sync(0xffffffffu, eidl, j + 1);
                sC = __shfl_sync(0xffffffffu, srcl, j + 1);
                rC = __shfl_sync(0xffffffffu, rell, j + 1);
                k4n = g_k[(size_t)sC * 32 + lane];
                v4n = g_v[(size_t)sC * 32 + lane];
                m4n = msg4[(size_t)eC * 32 + lane];
                xmn = msg4[(size_t)eC * 32 + (lane ^ 16)];
            }

            float4 ev;
            ev.x = __cosf(rel * tw4.x + tb4.x);
            ev.y = __cosf(rel * tw4.y + tb4.y);
            ev.z = __cosf(rel * tw4.z + tb4.z);
            ev.w = __cosf(rel * tw4.w + tb4.w);

            float qk = dot4(q4, k4);
            float4 Aa = (lane < 16) ? ev : xm;
            float4 Ab = (lane < 16) ? xm : ev;
            float pb = dot4(zb, Ab) + qk;
            float p0 = dot4(za, Aa) + ((lane < 16) ? pb : 0.f);
            float p1 = dot4(zc, m4) + ((lane < 16) ? 0.f : pb);
            #pragma unroll
            for (int o = 16; o >= 1; o >>= 1) {
                p0 += __shfl_xor_sync(0xffffffffu, p0, o);
                p1 += __shfl_xor_sync(0xffffffffu, p1, o);
            }

            float w0 = __expf(0.125f * p0);
            float w1 = __expf(0.125f * p1);

            float sc = (lane < 16) ? w0 : w1;
            aT.x += sc * ev.x; aT.y += sc * ev.y; aT.z += sc * ev.z; aT.w += sc * ev.w;
            aV.x += sc * v4.x; aV.y += sc * v4.y; aV.z += sc * v4.z; aV.w += sc * v4.w;
            aM0.x += w0 * m4.x; aM0.y += w0 * m4.y; aM0.z += w0 * m4.z; aM0.w += w0 * m4.w;
            aM1.x += w1 * m4.x; aM1.y += w1 * m4.y; aM1.z += w1 * m4.z; aM1.w += w1 * m4.w;
            s0 += w0; s1 += w1;
        }
    }

    g_aggT[(size_t)dst * 32 + lane] = aT;
    g_aggV[(size_t)dst * 32 + lane] = aV;
    g_aggM[(size_t)dst * 64 + lane]      = aM0;
    g_aggM[(size_t)dst * 64 + 32 + lane] = aM1;
    if (lane == 0) g_asum[dst] = make_float2(s0, s1);
}

// ---------------------------------------------------------------------------
// K3: out[n,h,c] += (aggV + sum_d aggE[n,h,d]*We[d,j]) / asum[n,h]
// We transposed in smem (stride 204: 16B-aligned, phase-conflict-free .128),
// vectorized dot4 over d-quads, aggregates broadcast from smem.
// ---------------------------------------------------------------------------
__global__ void k_final(const float* __restrict__ We, float* __restrict__ out)
{
    extern __shared__ float smf[];
    float* WeT = smf;                 // [128][204]  WeT[j*204+d] = We[d*128+j]
    float* sA  = smf + 128 * 204;     // [4 nodes][400]: h*192 + d
    float* sS  = sA + 4 * 400;        // 8 asums
    const int t = threadIdx.x;        // 128
    const int j = t, h = t >> 6;

    // fill transposed We: each thread owns row j (coalesced global reads)
    for (int d = 0; d < 192; d++)
        WeT[j * 204 + d] = We[d * 128 + j];

    const float4* w4 = (const float4*)(WeT + j * 204);

    for (int q0 = blockIdx.x * 4; q0 < NN; q0 += gridDim.x * 4) {
        __syncthreads();
        for (int i = t; i < 384; i += 128) {
            int ni = i / 96, m = i % 96;
            int node = q0 + ni;
            int hh = m / 48, d4 = m % 48;
            float4 val = (d4 < 16) ? g_aggT[(size_t)node * 32 + hh * 16 + d4]
                                   : g_aggM[(size_t)node * 64 + hh * 32 + (d4 - 16)];
            *(float4*)&sA[ni * 400 + hh * 192 + d4 * 4] = val;
        }
        if (t < 8) sS[t] = ((const float*)g_asum)[(size_t)(q0 + (t >> 1)) * 2 + (t & 1)];
        __syncthreads();

        const float4* a0 = (const float4*)(sA + 0 * 400 + h * 192);
        const float4* a1 = (const float4*)(sA + 1 * 400 + h * 192);
        const float4* a2 = (const float4*)(sA + 2 * 400 + h * 192);
        const float4* a3 = (const float4*)(sA + 3 * 400 + h * 192);
        float acc0 = 0.f, acc1 = 0.f, acc2 = 0.f, acc3 = 0.f;
        #pragma unroll 4
        for (int dq = 0; dq < 48; dq++) {
            float4 wv = w4[dq];
            acc0 += dot4(wv, a0[dq]);
            acc1 += dot4(wv, a1[dq]);
            acc2 += dot4(wv, a2[dq]);
            acc3 += dot4(wv, a3[dq]);
        }

        const float* gv = (const float*)g_aggV;
        size_t n0 = (size_t)q0;
        out[(n0 + 0) * 128 + j] += (gv[(n0 + 0) * 128 + j] + acc0) * (1.f / (sS[0 + h] + 1e-16f));
        out[(n0 + 1) * 128 + j] += (gv[(n0 + 1) * 128 + j] + acc1) * (1.f / (sS[2 + h] + 1e-16f));
        out[(n0 + 2) * 128 + j] += (gv[(n0 + 2) * 128 + j] + acc2) * (1.f / (sS[4 + h] + 1e-16f));
        out[(n0 + 3) * 128 + j] += (gv[(n0 + 3) * 128 + j] + acc3) * (1.f / (sS[6 + h] + 1e-16f));
    }
}

// ---------------------------------------------------------------------------
extern "C" void kernel_launch(void* const* d_in, const int* in_sizes, int n_in,
                              void* d_out, int out_size)
{
    const float* x  = (const float*)d_in[0];
    const float* lu = (const float*)d_in[1];
    const float* tt = (const float*)d_in[2];
    const float* msg = (const float*)d_in[3];
    const float* tw = (const float*)d_in[4];
    const float* tb = (const float*)d_in[5];
    const float* Wq = (const float*)d_in[6];
    const float* bq = (const float*)d_in[7];
    const float* Wk = (const float*)d_in[8];
    const float* bk = (const float*)d_in[9];
    const float* Wv = (const float*)d_in[10];
    const float* bv = (const float*)d_in[11];
    const float* We = (const float*)d_in[12];
    const float* Ws = (const float*)d_in[13];
    const float* bs = (const float*)d_in[14];
    const void* ei  = d_in[15];
    float* out = (float*)d_out;

    const int FINAL_SMEM = (128 * 204 + 4 * 400 + 8) * 4;   // 110880
    cudaFuncSetAttribute(k_final, cudaFuncAttributeMaxDynamicSharedMemorySize, FINAL_SMEM);

    void* pcnt;
    cudaGetSymbolAddress(&pcnt, g_cnt);
    cudaMemsetAsync(pcnt, 0, NN * sizeof(int));

    const int NCHUNK = (NN + 511) / 512;   // 98

    k_detect<<<1, 1>>>((const int*)ei);
    k_prep<<<452, 256>>>(Wq, bq, Wk, bk, Wv, bv, Ws, bs, We);
    k_gemm<<<dim3(391, 7, 1), 256>>>(x, out);
    k_hist<<<(EE + 255) / 256, 256>>>(ei);
    k_scanA<<<NCHUNK, 512>>>();
    k_scanB<<<1, 32>>>(NCHUNK);
    k_scanC<<<NCHUNK, 512>>>();
    k_scatter<<<(EE + 255) / 256, 256>>>(ei);
    k_edge2<<<(NN + 7) / 8, 256>>>(ei, tt, lu, (const float4*)msg, tw, tb);
    k_final<<<592, 128, FINAL_SMEM>>>(We, out);
}

// round 10
// speedup vs baseline: 1.1051x; 1.1051x over previous
#include <cuda_runtime.h>
#include <math.h>

#define NN 50000
#define EE 500000

// node-space tables
__device__ __align__(16) float4 g_q[NN * 32];
__device__ __align__(16) float4 g_k[NN * 32];
__device__ __align__(16) float4 g_v[NN * 32];
__device__ __align__(16) float4 g_z[NN * 96];      // [n][2][192] flat [n][384]
// per-dst aggregates (written once by k_edge2)
__device__ __align__(16) float4 g_aggT[NN * 32];   // [n][2][64]   sum w*enc
__device__ __align__(16) float4 g_aggM[NN * 64];   // [n][2][128]  sum w*msg
__device__ __align__(16) float4 g_aggV[NN * 32];   // [n][2][64]   sum w*v[src]
__device__ __align__(8)  float2 g_asum[NN];        // [n][2]       sum w
__device__ int g_is64;
// combined weights: cols [q(0) k(128) v(256) skip(384)]
__device__ __align__(16) float g_Wall[128 * 512];
__device__ __align__(16) float g_ball[512];
// transposed We per head: g_WeT[h][c][d] = We[d*128 + h*64 + c]
__device__ __align__(16) float g_WeT[2 * 64 * 192];
// counting-sort scratch
__device__ int g_cnt[NN];
__device__ int g_offA[NN];
__device__ int g_bsum[128];
__device__ int g_bpre[128];
__device__ int g_off[NN + 1];
__device__ int g_pos[NN];
__device__ int g_eid[EE];

static __device__ __forceinline__ float dot4(float4 a, float4 b) {
    return a.x * b.x + a.y * b.y + a.z * b.z + a.w * b.w;
}

// ---------------------------------------------------------------------------
__global__ void k_detect(const int* __restrict__ ei32) {
    int odd_or = 0;
    #pragma unroll
    for (int i = 1; i < 64; i += 2) odd_or |= ei32[i];
    g_is64 = (odd_or == 0) ? 1 : 0;
}

// ---------------------------------------------------------------------------
// Kp: Wall [128][512] copy + bias [512] + transposed We table.
// ---------------------------------------------------------------------------
__global__ void k_prep(const float* __restrict__ Wq, const float* __restrict__ bq,
                       const float* __restrict__ Wk, const float* __restrict__ bk,
                       const float* __restrict__ Wv, const float* __restrict__ bv,
                       const float* __restrict__ Ws, const float* __restrict__ bs,
                       const float* __restrict__ We)
{
    int u = blockIdx.x * 256 + threadIdx.x;
    if (u < 128 * 512) {
        int j = u >> 9, c = u & 511;
        const float* src = (c < 128) ? Wq : (c < 256) ? Wk : (c < 384) ? Wv : Ws;
        g_Wall[u] = src[j * 128 + (c & 127)];
    } else if (u < 128 * 512 + 2 * 64 * 192) {
        int v = u - 128 * 512;
        int h = v / 12288, r = v % 12288;
        int c = r / 192, d = r % 192;
        g_WeT[v] = We[d * 128 + h * 64 + c];
    } else if (u < 128 * 512 + 2 * 64 * 192 + 512) {
        int c = u - (128 * 512 + 2 * 64 * 192);
        const float* src = (c < 128) ? bq : (c < 256) ? bk : (c < 384) ? bv : bs;
        g_ball[c] = src[c & 127];
    }
}

// ---------------------------------------------------------------------------
// K1: node GEMM [50000,128] @ [128,512] (q,k,v,skip). Tile 128x128, 8x8/thr.
// ---------------------------------------------------------------------------
__global__ void __launch_bounds__(256, 2)
k_gemm(const float* __restrict__ x, float* __restrict__ out)
{
    __shared__ float xs[32][132];   // [k][m] transposed x panel
    __shared__ float ws[32][128];   // [k][n]
    const int t = threadIdx.x;
    const int y = blockIdx.y;
    const int col0 = y * 128;

    float* dptr;
    if      (y == 0) dptr = (float*)g_q;
    else if (y == 1) dptr = (float*)g_k;
    else if (y == 2) dptr = (float*)g_v;
    else             dptr = out;

    const int m0 = blockIdx.x * 128;
    const float4* x4 = (const float4*)x;
    const int tn = t & 15, tm = t >> 4;

    float4 acc[8][2];
    #pragma unroll
    for (int r = 0; r < 8; r++) { acc[r][0] = make_float4(0.f,0.f,0.f,0.f); acc[r][1] = acc[r][0]; }

#define FMA4(A, S, Bv) { A.x += (S)*(Bv).x; A.y += (S)*(Bv).y; A.z += (S)*(Bv).z; A.w += (S)*(Bv).w; }
    for (int k0 = 0; k0 < 128; k0 += 32) {
        #pragma unroll
        for (int i = t; i < 1024; i += 256) {
            int m = i >> 3, c4 = i & 7;
            int node = m0 + m;
            float4 v = (node < NN) ? x4[(size_t)node * 32 + (k0 >> 2) + c4]
                                   : make_float4(0.f, 0.f, 0.f, 0.f);
            int kk = c4 * 4;
            xs[kk + 0][m] = v.x; xs[kk + 1][m] = v.y;
            xs[kk + 2][m] = v.z; xs[kk + 3][m] = v.w;
        }
        #pragma unroll
        for (int i = t; i < 1024; i += 256) {
            int kk = i >> 5, c4 = i & 31;
            *(float4*)&ws[kk][c4 * 4] = *(const float4*)&g_Wall[(size_t)(k0 + kk) * 512 + col0 + c4 * 4];
        }
        __syncthreads();

        #pragma unroll
        for (int kk = 0; kk < 32; kk++) {
            float4 a0 = *(const float4*)&xs[kk][tm * 8];
            float4 a1 = *(const float4*)&xs[kk][tm * 8 + 4];
            float4 b0 = *(const float4*)&ws[kk][tn * 8];
            float4 b1 = *(const float4*)&ws[kk][tn * 8 + 4];
            FMA4(acc[0][0], a0.x, b0); FMA4(acc[0][1], a0.x, b1);
            FMA4(acc[1][0], a0.y, b0); FMA4(acc[1][1], a0.y, b1);
            FMA4(acc[2][0], a0.z, b0); FMA4(acc[2][1], a0.z, b1);
            FMA4(acc[3][0], a0.w, b0); FMA4(acc[3][1], a0.w, b1);
            FMA4(acc[4][0], a1.x, b0); FMA4(acc[4][1], a1.x, b1);
            FMA4(acc[5][0], a1.y, b0); FMA4(acc[5][1], a1.y, b1);
            FMA4(acc[6][0], a1.z, b0); FMA4(acc[6][1], a1.z, b1);
            FMA4(acc[7][0], a1.w, b0); FMA4(acc[7][1], a1.w, b1);
        }
        __syncthreads();
    }

    float4 bb0 = *(const float4*)&g_ball[col0 + tn * 8];
    float4 bb1 = *(const float4*)&g_ball[col0 + tn * 8 + 4];
    #pragma unroll
    for (int r = 0; r < 8; r++) {
        int node = m0 + tm * 8 + r;
        if (node >= NN) break;
        float4 o0 = acc[r][0]; o0.x += bb0.x; o0.y += bb0.y; o0.z += bb0.z; o0.w += bb0.w;
        float4 o1 = acc[r][1]; o1.x += bb1.x; o1.y += bb1.y; o1.z += bb1.z; o1.w += bb1.w;
        float* p = dptr + (size_t)node * 128 + tn * 8;
        *(float4*)p = o0;
        *(float4*)(p + 4) = o1;
    }
}

// ---------------------------------------------------------------------------
// K1b: z GEMM from q: z[n,h,d] = sum_c q[n,h,c] * WeT[h][c][d], k=64.
// Tile 128 nodes x 64 cols; grid y = head*3 + ntile; 8x4 per thread.
// Bias is implicit (q already contains bq).
// ---------------------------------------------------------------------------
__global__ void __launch_bounds__(256, 2)
k_gemmz()
{
    __shared__ float xs[32][132];   // [k][m] transposed q_h panel
    __shared__ float ws[32][68];    // [k][n]
    const int t = threadIdx.x;
    const int head = blockIdx.y / 3;
    const int nt = blockIdx.y % 3;
    const int col0 = nt * 64;
    const int m0 = blockIdx.x * 128;

    const float4* q4 = (const float4*)g_q;
    const float4* wt4 = (const float4*)(g_WeT + head * 12288);
    const int tn = t & 15, tm = t >> 4;

    float4 acc[8];
    #pragma unroll
    for (int r = 0; r < 8; r++) acc[r] = make_float4(0.f, 0.f, 0.f, 0.f);

    for (int k0 = 0; k0 < 64; k0 += 32) {
        #pragma unroll
        for (int i = t; i < 1024; i += 256) {
            int m = i >> 3, c4 = i & 7;
            int node = m0 + m;
            float4 v = (node < NN) ? q4[(size_t)node * 32 + head * 16 + (k0 >> 2) + c4]
                                   : make_float4(0.f, 0.f, 0.f, 0.f);
            int kk = c4 * 4;
            xs[kk + 0][m] = v.x; xs[kk + 1][m] = v.y;
            xs[kk + 2][m] = v.z; xs[kk + 3][m] = v.w;
        }
        #pragma unroll
        for (int i = t; i < 512; i += 256) {
            int kk = i >> 4, c4 = i & 15;
            *(float4*)&ws[kk][c4 * 4] = wt4[(size_t)(k0 + kk) * 48 + nt * 16 + c4];
        }
        __syncthreads();

        #pragma unroll
        for (int kk = 0; kk < 32; kk++) {
            float4 a0 = *(const float4*)&xs[kk][tm * 8];
            float4 a1 = *(const float4*)&xs[kk][tm * 8 + 4];
            float4 b0 = *(const float4*)&ws[kk][tn * 4];
            FMA4(acc[0], a0.x, b0);
            FMA4(acc[1], a0.y, b0);
            FMA4(acc[2], a0.z, b0);
            FMA4(acc[3], a0.w, b0);
            FMA4(acc[4], a1.x, b0);
            FMA4(acc[5], a1.y, b0);
            FMA4(acc[6], a1.z, b0);
            FMA4(acc[7], a1.w, b0);
        }
        __syncthreads();
    }
#undef FMA4

    float* zf = (float*)g_z;
    #pragma unroll
    for (int r = 0; r < 8; r++) {
        int node = m0 + tm * 8 + r;
        if (node >= NN) break;
        *(float4*)&zf[(size_t)node * 384 + head * 192 + col0 + tn * 4] = acc[r];
    }
}

// ---------------------------------------------------------------------------
// Counting sort by dst
// ---------------------------------------------------------------------------
__global__ void k_hist(const void* __restrict__ ei) {
    const int e = blockIdx.x * 256 + threadIdx.x;
    if (e >= EE) return;
    int dst = g_is64 ? (int)((const long long*)ei)[EE + e] : ((const int*)ei)[EE + e];
    atomicAdd(&g_cnt[dst], 1);
}

__global__ void k_scanA() {
    __shared__ int s[512];
    const int tid = threadIdx.x;
    const int i = blockIdx.x * 512 + tid;
    int c = (i < NN) ? g_cnt[i] : 0;
    s[tid] = c;
    __syncthreads();
    #pragma unroll
    for (int o = 1; o < 512; o <<= 1) {
        int v = (tid >= o) ? s[tid - o] : 0;
        __syncthreads();
        if (tid >= o) s[tid] += v;
        __syncthreads();
    }
    if (i < NN) g_offA[i] = s[tid] - c;
    if (tid == 511) g_bsum[blockIdx.x] = s[511];
}

__global__ void k_scanB(int nchunks) {
    if (threadIdx.x == 0) {
        int run = 0;
        for (int b = 0; b < nchunks; b++) { g_bpre[b] = run; run += g_bsum[b]; }
        g_off[NN] = EE;
    }
}

__global__ void k_scanC() {
    const int i = blockIdx.x * 512 + threadIdx.x;
    if (i < NN) {
        int v = g_offA[i] + g_bpre[blockIdx.x];
        g_off[i] = v;
        g_pos[i] = v;
    }
}

__global__ void k_scatter(const void* __restrict__ ei) {
    const int e = blockIdx.x * 256 + threadIdx.x;
    if (e >= EE) return;
    int dst = g_is64 ? (int)((const long long*)ei)[EE + e] : ((const int*)ei)[EE + e];
    int p = atomicAdd(&g_pos[dst], 1);
    g_eid[p] = e;
}

// ---------------------------------------------------------------------------
// K2: warp per dst segment, lane-batched edge prefetch (MLP=32), register
// accumulation, single write.  (exact R5 version)
// ---------------------------------------------------------------------------
__global__ void __launch_bounds__(256)
k_edge2(const void* __restrict__ ei,
        const float* __restrict__ tt,
        const float* __restrict__ lu,
        const float4* __restrict__ msg4,
        const float* __restrict__ tw,
        const float* __restrict__ tb)
{
    const int w = threadIdx.x >> 5, lane = threadIdx.x & 31;
    const int dst = blockIdx.x * 8 + w;
    if (dst >= NN) return;
    const int is64 = g_is64;
    const int beg = g_off[dst], end = g_off[dst + 1];

    const int lq = lane & 15;
    const float4 tw4 = ((const float4*)tw)[lq];
    const float4 tb4 = ((const float4*)tb)[lq];
    const float4 q4 = g_q[(size_t)dst * 32 + lane];
    const size_t zb0 = (size_t)dst * 96;
    const float4 za = g_z[zb0 + lane];
    const float4 zb = g_z[zb0 + 32 + lane];
    const float4 zc = g_z[zb0 + 64 + lane];

    float4 aT = make_float4(0.f, 0.f, 0.f, 0.f), aV = aT, aM0 = aT, aM1 = aT;
    float s0 = 0.f, s1 = 0.f;

    for (int base = beg; base < end; base += 32) {
        const int cnt = min(32, end - base);
        int eidl = 0, srcl = 0; float rell = 0.f;
        if (lane < cnt) {
            eidl = g_eid[base + lane];
            long long s = is64 ? ((const long long*)ei)[eidl]
                               : (long long)((const int*)ei)[eidl];
            srcl = (int)s;
            rell = tt[eidl] - lu[s];
        }

        for (int j = 0; j < cnt; j++) {
            const int eid = __shfl_sync(0xffffffffu, eidl, j);
            const int src = __shfl_sync(0xffffffffu, srcl, j);
            const float rel = __shfl_sync(0xffffffffu, rell, j);

            const size_t mb = (size_t)eid * 32;
            float4 k4 = g_k[(size_t)src * 32 + lane];
            float4 v4 = g_v[(size_t)src * 32 + lane];
            float4 m4 = msg4[mb + lane];

            float4 ev;
            ev.x = __cosf(rel * tw4.x + tb4.x);
            ev.y = __cosf(rel * tw4.y + tb4.y);
            ev.z = __cosf(rel * tw4.z + tb4.z);
            ev.w = __cosf(rel * tw4.w + tb4.w);

            float qk = dot4(q4, k4);
            float4 Aa = (lane < 16) ? ev : msg4[mb + lane - 16];
            float4 Ab = (lane < 16) ? msg4[mb + lane + 16] : ev;
            float pb = dot4(zb, Ab) + qk;
            float p0 = dot4(za, Aa) + ((lane < 16) ? pb : 0.f);
            float p1 = dot4(zc, m4) + ((lane < 16) ? 0.f : pb);
            #pragma unroll
            for (int o = 16; o >= 1; o >>= 1) {
                p0 += __shfl_xor_sync(0xffffffffu, p0, o);
                p1 += __shfl_xor_sync(0xffffffffu, p1, o);
            }

            float w0 = __expf(0.125f * p0);
            float w1 = __expf(0.125f * p1);

            float sc = (lane < 16) ? w0 : w1;
            aT.x += sc * ev.x; aT.y += sc * ev.y; aT.z += sc * ev.z; aT.w += sc * ev.w;
            aV.x += sc * v4.x; aV.y += sc * v4.y; aV.z += sc * v4.z; aV.w += sc * v4.w;
            aM0.x += w0 * m4.x; aM0.y += w0 * m4.y; aM0.z += w0 * m4.z; aM0.w += w0 * m4.w;
            aM1.x += w1 * m4.x; aM1.y += w1 * m4.y; aM1.z += w1 * m4.z; aM1.w += w1 * m4.w;
            s0 += w0; s1 += w1;
        }
    }

    g_aggT[(size_t)dst * 32 + lane] = aT;
    g_aggV[(size_t)dst * 32 + lane] = aV;
    g_aggM[(size_t)dst * 64 + lane]      = aM0;
    g_aggM[(size_t)dst * 64 + 32 + lane] = aM1;
    if (lane == 0) g_asum[dst] = make_float2(s0, s1);
}

// ---------------------------------------------------------------------------
// K3: out[n,h,c] += (aggV[n,h,c] + sum_d aggE[n,h,d]*We[d,h*64+c]) / asum[n,h]
// (exact R5 version)
// ---------------------------------------------------------------------------
__global__ void k_final(const float* __restrict__ We, float* __restrict__ out)
{
    extern __shared__ float smf[];
    float* WeS = smf;                // 192 x 132
    float* sA  = smf + 192 * 132;    // 4 x 392
    float* sS  = sA + 4 * 392;       // 8 asums
    const int t = threadIdx.x;       // 128

    const float4* We4 = (const float4*)We;
    for (int i = t; i < 192 * 32; i += 128) {
        int d = i >> 5, c4 = i & 31;
        ((float4*)(WeS + d * 132))[c4] = We4[i];
    }

    const int j = t, h = t >> 6;
    for (int q0 = blockIdx.x * 4; q0 < NN; q0 += gridDim.x * 4) {
        __syncthreads();
        for (int i = t; i < 4 * 96; i += 128) {
            int ni = i / 96, m = i % 96;
            int node = q0 + ni;
            int hh = m / 48, d4 = m % 48;
            float4 val = (d4 < 16) ? g_aggT[(size_t)node * 32 + hh * 16 + d4]
                                   : g_aggM[(size_t)node * 64 + hh * 32 + (d4 - 16)];
            *(float4*)&sA[ni * 392 + hh * 196 + d4 * 4] = val;
        }
        if (t < 8) sS[t] = ((const float*)g_asum)[(size_t)(q0 + (t >> 1)) * 2 + (t & 1)];
        __syncthreads();

        float acc0 = 0.f, acc1 = 0.f, acc2 = 0.f, acc3 = 0.f;
        const float* a0 = sA + 0 * 392 + h * 196;
        const float* a1 = sA + 1 * 392 + h * 196;
        const float* a2 = sA + 2 * 392 + h * 196;
        const float* a3 = sA + 3 * 392 + h * 196;
        #pragma unroll 4
        for (int d = 0; d < 192; d++) {
            float wv = WeS[d * 132 + j];
            acc0 += wv * a0[d];
            acc1 += wv * a1[d];
            acc2 += wv * a2[d];
            acc3 += wv * a3[d];
        }

        const float* gv = (const float*)g_aggV;
        size_t n0 = (size_t)q0;
        out[(n0 + 0) * 128 + j] += (gv[(n0 + 0) * 128 + j] + acc0) * (1.f / (sS[0 + h] + 1e-16f));
        out[(n0 + 1) * 128 + j] += (gv[(n0 + 1) * 128 + j] + acc1) * (1.f / (sS[2 + h] + 1e-16f));
        out[(n0 + 2) * 128 + j] += (gv[(n0 + 2) * 128 + j] + acc2) * (1.f / (sS[4 + h] + 1e-16f));
        out[(n0 + 3) * 128 + j] += (gv[(n0 + 3) * 128 + j] + acc3) * (1.f / (sS[6 + h] + 1e-16f));
    }
}

// ---------------------------------------------------------------------------
extern "C" void kernel_launch(void* const* d_in, const int* in_sizes, int n_in,
                              void* d_out, int out_size)
{
    const float* x  = (const float*)d_in[0];
    const float* lu = (const float*)d_in[1];
    const float* tt = (const float*)d_in[2];
    const float* msg = (const float*)d_in[3];
    const float* tw = (const float*)d_in[4];
    const float* tb = (const float*)d_in[5];
    const float* Wq = (const float*)d_in[6];
    const float* bq = (const float*)d_in[7];
    const float* Wk = (const float*)d_in[8];
    const float* bk = (const float*)d_in[9];
    const float* Wv = (const float*)d_in[10];
    const float* bv = (const float*)d_in[11];
    const float* We = (const float*)d_in[12];
    const float* Ws = (const float*)d_in[13];
    const float* bs = (const float*)d_in[14];
    const void* ei  = d_in[15];
    float* out = (float*)d_out;

    cudaFuncSetAttribute(k_final, cudaFuncAttributeMaxDynamicSharedMemorySize, 107680);

    void* pcnt;
    cudaGetSymbolAddress(&pcnt, g_cnt);
    cudaMemsetAsync(pcnt, 0, NN * sizeof(int));

    const int NCHUNK = (NN + 511) / 512;   // 98

    k_detect<<<1, 1>>>((const int*)ei);
    k_prep<<<353, 256>>>(Wq, bq, Wk, bk, Wv, bv, Ws, bs, We);
    k_gemm<<<dim3(391, 4, 1), 256>>>(x, out);
    k_gemmz<<<dim3(391, 6, 1), 256>>>();
    k_hist<<<(EE + 255) / 256, 256>>>(ei);
    k_scanA<<<NCHUNK, 512>>>();
    k_scanB<<<1, 32>>>(NCHUNK);
    k_scanC<<<NCHUNK, 512>>>();
    k_scatter<<<(EE + 255) / 256, 256>>>(ei);
    k_edge2<<<(NN + 7) / 8, 256>>>(ei, tt, lu, (const float4*)msg, tw, tb);
    k_final<<<592, 128, 107680>>>(We, out);
}